// round 8
// baseline (speedup 1.0000x reference)
#include <cuda_runtime.h>
#include <cuda_bf16.h>

// NonMaximaSuppression2d: x (8, 64, 256, 256) fp32.
// out[p] = x[p] if x[p] > max(0, 8 replicate-padded neighbors) else 0.
//
// One warp = one 16-row strip (8 row-pairs); lane owns 8 cols (2x float4).
// 5-slot register row-ring: 4 rows live, 2 new rows loaded per pair,
// prefetched one iteration ahead (read amp 1.125x vs 2x in the per-pair
// kernel). Column-max formulation, 4 shuffles per pair.

#define H 256
#define W 256
#define WARPS_PER_BLOCK 8
#define NIMG (8 * 64)              // 512 images
#define STRIPS_PER_IMG 16          // 16 rows per strip
#define PAIRS 8                    // row-pairs per strip

__device__ __forceinline__ void load_row(const float* __restrict__ row,
                                         int lane, float v[8])
{
    const float4* p = (const float4*)row + lane * 2;
    float4 a = __ldg(p);
    float4 b = __ldg(p + 1);
    v[0] = a.x; v[1] = a.y; v[2] = a.z; v[3] = a.w;
    v[4] = b.x; v[5] = b.y; v[6] = b.z; v[7] = b.w;
}

// n[j] = max(cm[j-1], cm[j+1]) with replicate clamp at image edges.
__device__ __forceinline__ void hnb(const float cm[8], int lane, float n[8])
{
    float lf = __shfl_up_sync(0xffffffffu, cm[7], 1);
    if (lane == 0) lf = cm[0];                // replicate col 0
    float rt = __shfl_down_sync(0xffffffffu, cm[0], 1);
    if (lane == 31) rt = cm[7];               // replicate col 255

    n[0] = fmaxf(lf,    cm[1]);
#pragma unroll
    for (int j = 1; j < 7; j++)
        n[j] = fmaxf(cm[j-1], cm[j+1]);
    n[7] = fmaxf(cm[6], rt);
}

__global__ __launch_bounds__(32 * WARPS_PER_BLOCK, 4)
void nms2d_kernel(const float* __restrict__ x, float* __restrict__ out)
{
    const int warp = threadIdx.x >> 5;
    const int lane = threadIdx.x & 31;
    const int s    = blockIdx.x * WARPS_PER_BLOCK + warp;   // global strip id
    const int b    = s >> 4;                                // image
    const int Y    = (s & 15) << 4;                         // strip start row

    const float* __restrict__ base  = x   + (size_t)b * (H * W);
    float*       __restrict__ obase = out + (size_t)b * (H * W);

    // Row ring: slot r%5 holds global row (Y-1+r). Pair i uses r = 2i..2i+3.
    float buf[5][8];

    // Prologue: rows r=0..3  (Y-1 clamped at image top).
    {
        const int y0 = (Y > 0) ? Y - 1 : 0;
        load_row(base + (size_t)y0      * W, lane, buf[0]);
        load_row(base + (size_t)Y       * W, lane, buf[1]);
        load_row(base + (size_t)(Y + 1) * W, lane, buf[2]);
        load_row(base + (size_t)(Y + 2) * W, lane, buf[3]);
    }

#pragma unroll
    for (int i = 0; i < PAIRS; i++) {
        float* v0 = buf[(2 * i)     % 5];
        float* v1 = buf[(2 * i + 1) % 5];
        float* v2 = buf[(2 * i + 2) % 5];
        float* v3 = buf[(2 * i + 3) % 5];

        // Prefetch (pair i+1, first row) into the fresh slot (2i+4)%5.
        if (i < PAIRS - 1) {
            const int ya = Y + 2 * i + 3;                    // <= Y+15, in range
            load_row(base + (size_t)ya * W, lane, buf[(2 * i + 4) % 5]);
        }

        // Column maxes: v0 and v3 raw die here.
        float q02[8], q13[8], cma[8], cmb[8];
#pragma unroll
        for (int j = 0; j < 8; j++) {
            q02[j] = fmaxf(v0[j], v2[j]);
            q13[j] = fmaxf(v1[j], v3[j]);
            cma[j] = fmaxf(q02[j], v1[j]);
            cmb[j] = fmaxf(q13[j], v2[j]);
        }

        // Prefetch (pair i+1, second row) into v0's slot — v0 is dead now.
        if (i < PAIRS - 1) {
            int yb = Y + 2 * i + 4;
            if (yb > H - 1) yb = H - 1;                      // bottom clamp
            load_row(base + (size_t)yb * W, lane, buf[(2 * i) % 5]);
        }

        float na[8], nb[8];
        hnb(cma, lane, na);
        hnb(cmb, lane, nb);

        const int yo = Y + 2 * i;

        float oa[8];
#pragma unroll
        for (int j = 0; j < 8; j++) {
            float mx = fmaxf(na[j], fmaxf(q02[j], 0.0f));
            oa[j] = (v1[j] > mx) ? v1[j] : 0.0f;
        }
        {
            float4* pa = (float4*)(obase + (size_t)yo * W) + lane * 2;
            pa[0] = make_float4(oa[0], oa[1], oa[2], oa[3]);
            pa[1] = make_float4(oa[4], oa[5], oa[6], oa[7]);
        }

        float ob[8];
#pragma unroll
        for (int j = 0; j < 8; j++) {
            float mx = fmaxf(nb[j], fmaxf(q13[j], 0.0f));
            ob[j] = (v2[j] > mx) ? v2[j] : 0.0f;
        }
        {
            float4* pb = (float4*)(obase + (size_t)(yo + 1) * W) + lane * 2;
            pb[0] = make_float4(ob[0], ob[1], ob[2], ob[3]);
            pb[1] = make_float4(ob[4], ob[5], ob[6], ob[7]);
        }
    }
}

extern "C" void kernel_launch(void* const* d_in, const int* in_sizes, int n_in,
                              void* d_out, int out_size)
{
    const float* x = (const float*)d_in[0];
    float* out = (float*)d_out;

    const int total_strips = NIMG * STRIPS_PER_IMG;        // 8192 warps
    const int blocks = total_strips / WARPS_PER_BLOCK;     // 1024 blocks
    nms2d_kernel<<<blocks, 32 * WARPS_PER_BLOCK>>>(x, out);
}

// round 9
// speedup vs baseline: 1.1875x; 1.1875x over previous
#include <cuda_runtime.h>
#include <cuda_bf16.h>

// NonMaximaSuppression2d: x (8, 64, 256, 256) fp32.
// out[p] = x[p] if x[p] > max(0, 8 replicate-padded neighbors) else 0.
//
// One warp = TWO adjacent 256-wide output rows (flat independent work items;
// rolling/strip variants are issue-starved — measured R2/R8).
// Lane owns 8 cols (2x float4). 8 independent LDG.128/thread, MLP=8.
// Column-max formulation, 4 shuffles/warp.
// Addressing is fully linear in the work-item id: pair r covers elements
// [512*r, 512*r+512); halos are +-256 with clamps only at image seams.
// All index math is 32-bit (33.5M elements < 2^31).

#define WARPS_PER_BLOCK 8
#define TOTAL_PAIRS (512 * 128)   // 512 images x 128 row-pairs

__device__ __forceinline__ void load_row(const float* __restrict__ p8,
                                         float v[8])
{
    const float4* p = (const float4*)p8;
    float4 a = __ldg(p);
    float4 b = __ldg(p + 1);
    v[0] = a.x; v[1] = a.y; v[2] = a.z; v[3] = a.w;
    v[4] = b.x; v[5] = b.y; v[6] = b.z; v[7] = b.w;
}

// n[j] = max(cm[j-1], cm[j+1]) with replicate clamp at image edges.
__device__ __forceinline__ void hnb(const float cm[8], int lane, float n[8])
{
    float lf = __shfl_up_sync(0xffffffffu, cm[7], 1);
    if (lane == 0) lf = cm[0];                // replicate col 0
    float rt = __shfl_down_sync(0xffffffffu, cm[0], 1);
    if (lane == 31) rt = cm[7];               // replicate col 255

    n[0] = fmaxf(lf,    cm[1]);
#pragma unroll
    for (int j = 1; j < 7; j++)
        n[j] = fmaxf(cm[j-1], cm[j+1]);
    n[7] = fmaxf(cm[6], rt);
}

__global__ __launch_bounds__(32 * WARPS_PER_BLOCK, 6)
void nms2d_kernel(const float* __restrict__ x, float* __restrict__ out)
{
    const int warp = threadIdx.x >> 5;
    const int lane = threadIdx.x & 31;
    const int r    = blockIdx.x * WARPS_PER_BLOCK + warp;  // row-pair id
    const int pim  = r & 127;                              // pair index in image

    const int lo   = lane * 8;            // lane element offset within a row
    const int mid0 = r * 512 + lo;        // row yp   (lane-local)
    const int mid1 = mid0 + 256;          // row yp+1

    const int top  = (pim == 0)   ? mid0 : mid0 - 256;   // clamp image top
    const int bot  = (pim == 127) ? mid1 : mid1 + 256;   // clamp image bottom

    // 8 independent LDG.128 — all issued before any dependent math.
    float v0[8], v1[8], v2[8], v3[8];
    load_row(x + top,  v0);
    load_row(x + mid0, v1);
    load_row(x + mid1, v2);
    load_row(x + bot,  v3);

    // Column maxes; v0 and v3 die here.
    float q02[8], q13[8], cma[8], cmb[8];
#pragma unroll
    for (int j = 0; j < 8; j++) {
        q02[j] = fmaxf(v0[j], v2[j]);
        q13[j] = fmaxf(v1[j], v3[j]);
        cma[j] = fmaxf(q02[j], v1[j]);
        cmb[j] = fmaxf(q13[j], v2[j]);
    }

    float na[8], nb[8];
    hnb(cma, lane, na);
    hnb(cmb, lane, nb);

    float oa[8], ob[8];
#pragma unroll
    for (int j = 0; j < 8; j++) {
        float mxa = fmaxf(na[j], fmaxf(q02[j], 0.0f));
        oa[j] = (v1[j] > mxa) ? v1[j] : 0.0f;
        float mxb = fmaxf(nb[j], fmaxf(q13[j], 0.0f));
        ob[j] = (v2[j] > mxb) ? v2[j] : 0.0f;
    }

    float4* pa = (float4*)(out + mid0);
    pa[0] = make_float4(oa[0], oa[1], oa[2], oa[3]);
    pa[1] = make_float4(oa[4], oa[5], oa[6], oa[7]);
    float4* pb = (float4*)(out + mid1);
    pb[0] = make_float4(ob[0], ob[1], ob[2], ob[3]);
    pb[1] = make_float4(ob[4], ob[5], ob[6], ob[7]);
}

extern "C" void kernel_launch(void* const* d_in, const int* in_sizes, int n_in,
                              void* d_out, int out_size)
{
    const float* x = (const float*)d_in[0];
    float* out = (float*)d_out;

    const int blocks = TOTAL_PAIRS / WARPS_PER_BLOCK;    // 8192 blocks
    nms2d_kernel<<<blocks, 32 * WARPS_PER_BLOCK>>>(x, out);
}